// round 17
// baseline (speedup 1.0000x reference)
#include <cuda_runtime.h>
#include <cuda_fp16.h>
#include <cstdint>

#define NR 16384
#define NT 128                    // 128-row strips
#define TOT (NT * (NT + 1) / 2)   // 8256 triangle tiles
#define NCTA 296                  // 2 CTAs/SM x 148 SMs, all co-resident
// exp(sim/T) = exp2(sim * 1/(T*ln2)), T=0.5 -> scale rows by sqrt(2.885390...)
#define SQRT_SCALE 1.6986436029926783f
#define E2C 7.389056098930650f    // exp(1/T) = e^2, exact diagonal term

#define ROWB 80                   // padded smem row stride (bytes)
#define TILE_B (128 * ROWB)       // 10240 B per tile buffer

__device__ unsigned short g_Q[NR * 32];   // e4m3 rows (64 fp8 = 32 ushort)
__device__ __half2 g_Y[NR * 32];          // f16 rows (numerator path)
__device__ float   g_RS[NR];              // row sums of exp2(arg)
__device__ float   g_sum;                 // global ratio accumulator
__device__ unsigned g_cnt;                // completion ticket
__device__ unsigned g_bar_flag;           // grid-barrier sense (monotonic)
__device__ unsigned g_bar_cnt;            // grid-barrier arrival counter

// ---------------------------------------------------------------------------
// Sense-reversing grid barrier. Safe: all NCTA blocks are co-resident
// (single wave at occupancy 2, enforced by __launch_bounds__ + 47KB smem).
// flag is monotonic -> graph-replay-safe; cnt self-resets each use.
// ---------------------------------------------------------------------------
__device__ __forceinline__ void grid_barrier() {
    __syncthreads();
    if (threadIdx.x == 0) {
        unsigned sense = *(volatile unsigned*)&g_bar_flag;  // read BEFORE arrive
        __threadfence();
        if (atomicAdd(&g_bar_cnt, 1u) == NCTA - 1) {
            g_bar_cnt = 0;
            __threadfence();
            *(volatile unsigned*)&g_bar_flag = sense + 1;
        } else {
            while (*(volatile unsigned*)&g_bar_flag == sense) { __nanosleep(32); }
        }
        __threadfence();
    }
    __syncthreads();
}

// ---------------------------------------------------------------------------
__device__ __forceinline__ void cp16(void* dst, const void* src) {
    unsigned d = (unsigned)__cvta_generic_to_shared(dst);
    asm volatile("cp.async.ca.shared.global [%0], [%1], 16;\n" ::"r"(d), "l"(src));
}

__device__ __forceinline__ void prefetch_tile(uint8_t* buf, int rowbase, int tid) {
    const char* src = (const char*)g_Q;
#pragma unroll
    for (int it = 0; it < 2; it++) {
        int u = tid + it * 256;               // 0..511 16B chunks
        int r = u >> 2, cdx = u & 3;
        cp16(buf + r * ROWB + cdx * 16,
             src + (size_t)(rowbase + r) * 64 + cdx * 16);
    }
}

#define MMA_PAIR(dst0, dst1, A, B)                                          \
    asm("mma.sync.aligned.m16n8k32.row.col.f16.e4m3.e4m3.f16 "              \
        "{%0,%1},{%2,%3,%4,%5},{%6,%7},{%0,%1};\n"                          \
        : "+r"(dst0), "+r"(dst1)                                            \
        : "r"((A)[0][0]), "r"((A)[0][1]), "r"((A)[0][2]), "r"((A)[0][3]),   \
          "r"((B)[0][0]), "r"((B)[0][1]));                                  \
    asm("mma.sync.aligned.m16n8k32.row.col.f16.e4m3.e4m3.f16 "              \
        "{%0,%1},{%2,%3,%4,%5},{%6,%7},{%0,%1};\n"                          \
        : "+r"(dst0), "+r"(dst1)                                            \
        : "r"((A)[1][0]), "r"((A)[1][1]), "r"((A)[1][2]), "r"((A)[1][3]),   \
          "r"((B)[1][0]), "r"((B)[1][1]));

#define CONSUME(src0, src1, pmf, ps)                                        \
    {                                                                       \
        unsigned e0, e1;                                                    \
        asm("ex2.approx.f16x2 %0, %1;" : "=r"(e0) : "r"(src0));             \
        asm("ex2.approx.f16x2 %0, %1;" : "=r"(e1) : "r"(src1));             \
        asm("add.f16x2 %0, %0, %1;" : "+r"(racc0[pmf]) : "r"(e0));          \
        asm("add.f16x2 %0, %0, %1;" : "+r"(racc1[pmf]) : "r"(e1));          \
        asm("add.f16x2 %0, %0, %1;" : "+r"(cacc[ps]) : "r"(e0));            \
        asm("add.f16x2 %0, %0, %1;" : "+r"(cacc[ps]) : "r"(e1));            \
    }

// ---------------------------------------------------------------------------
// Single fused kernel: normalize -> barrier -> triangular FP8 GEMM+exp2 row
// sums -> barrier -> pair ratios + loss. Tile loop identical to the proven
// 62us version (legacy-tensor floor — DO NOT TOUCH).
// ---------------------------------------------------------------------------
__global__ void __launch_bounds__(256, 2) k_all(const float* __restrict__ x,
                                                float* __restrict__ out) {
    __shared__ __align__(16) uint8_t bufA[2][TILE_B];
    __shared__ __align__(16) uint8_t bufB[2][TILE_B];
    __shared__ float red[2][128][4];
    __shared__ float cred[2][128][2];

    int tid  = threadIdx.x;
    int warp = tid >> 5, lane = tid & 31;

    // ---------------- Phase 1: normalize (4 rows/warp per task) ----------
    {
        int sr = lane >> 3;                    // sub-row 0..3
        int li = lane & 7;                     // lane within row
        int gw = blockIdx.x * 8 + warp;        // global warp id, 0..2367
        for (int t = gw; t < NR / 4; t += NCTA * 8) {
            int row = t * 4 + sr;
            const float4* xp = (const float4*)(x + (size_t)row * 64 + li * 8);
            float4 v0 = xp[0];
            float4 v1 = xp[1];
            float ss = v0.x * v0.x + v0.y * v0.y + v0.z * v0.z + v0.w * v0.w
                     + v1.x * v1.x + v1.y * v1.y + v1.z * v1.z + v1.w * v1.w;
#pragma unroll
            for (int o = 1; o < 8; o <<= 1) ss += __shfl_xor_sync(0xffffffffu, ss, o);
            float s = SQRT_SCALE * rsqrtf(fmaxf(ss, 1e-16f));
            float f[8] = {v0.x * s, v0.y * s, v0.z * s, v0.w * s,
                          v1.x * s, v1.y * s, v1.z * s, v1.w * s};
            __half2 h0 = __floats2half2_rn(f[0], f[1]);
            __half2 h1 = __floats2half2_rn(f[2], f[3]);
            __half2 h2 = __floats2half2_rn(f[4], f[5]);
            __half2 h3 = __floats2half2_rn(f[6], f[7]);
            uint4 hv;
            hv.x = *(unsigned*)&h0; hv.y = *(unsigned*)&h1;
            hv.z = *(unsigned*)&h2; hv.w = *(unsigned*)&h3;
            *(uint4*)(g_Y + (size_t)row * 32 + li * 4) = hv;
            unsigned short q0, q1, q2, q3;
            asm("cvt.rn.satfinite.e4m3x2.f32 %0, %1, %2;" : "=h"(q0) : "f"(f[1]), "f"(f[0]));
            asm("cvt.rn.satfinite.e4m3x2.f32 %0, %1, %2;" : "=h"(q1) : "f"(f[3]), "f"(f[2]));
            asm("cvt.rn.satfinite.e4m3x2.f32 %0, %1, %2;" : "=h"(q2) : "f"(f[5]), "f"(f[4]));
            asm("cvt.rn.satfinite.e4m3x2.f32 %0, %1, %2;" : "=h"(q3) : "f"(f[7]), "f"(f[6]));
            *(ushort4*)(g_Q + (size_t)row * 32 + li * 4) = make_ushort4(q0, q1, q2, q3);
            if (li == 0) g_RS[row] = 0.f;
        }
    }
    grid_barrier();                            // g_Q/g_Y/g_RS globally visible

    // ---------------- Phase 2: triangular tile loop (unchanged) ----------
    {
        int r = warp >> 2, c = warp & 3;       // row-group / column-group
        int rbase = r * 64;
        int g   = lane >> 2;                   // 0..7
        int tig = lane & 3;                    // 0..3

        int start = (int)(((long long)TOT * blockIdx.x) / NCTA);
        int end   = (int)(((long long)TOT * (blockIdx.x + 1)) / NCTA);

        int I = 0, acc = 0;
        while (acc + (NT - I) <= start) { acc += NT - I; I++; }
        int J = I + (start - acc);

        prefetch_tile(bufA[0], I * 128, tid);
        prefetch_tile(bufB[0], J * 128, tid);
        asm volatile("cp.async.commit_group;\n");

        for (int p = start; p < end; p++) {
            int buf = (p - start) & 1;
            int nI = I, nJ = J + 1;
            if (nJ == NT) { nI++; nJ = nI; }
            if (p + 1 < end) {
                prefetch_tile(bufA[buf ^ 1], nI * 128, tid);
                prefetch_tile(bufB[buf ^ 1], nJ * 128, tid);
                asm volatile("cp.async.commit_group;\n");
                asm volatile("cp.async.wait_group 1;\n");
            } else {
                asm volatile("cp.async.wait_group 0;\n");
            }
            __syncthreads();

            const uint8_t* smA = bufA[buf];
            const uint8_t* smB = bufB[buf];

            unsigned a[4][2][4];
#pragma unroll
            for (int mf = 0; mf < 4; mf++) {
#pragma unroll
                for (int kc = 0; kc < 2; kc++) {
                    const uint8_t* ap = smA + (rbase + mf * 16 + g) * ROWB + kc * 32 + tig * 4;
                    a[mf][kc][0] = *(const unsigned*)(ap);
                    a[mf][kc][1] = *(const unsigned*)(ap + 8 * ROWB);
                    a[mf][kc][2] = *(const unsigned*)(ap + 16);
                    a[mf][kc][3] = *(const unsigned*)(ap + 8 * ROWB + 16);
                }
            }
            unsigned b[4][2][2];
#pragma unroll
            for (int s = 0; s < 4; s++) {
                const uint8_t* bp = smB + ((c + s * 4) * 8 + g) * ROWB + tig * 4;
#pragma unroll
                for (int kc = 0; kc < 2; kc++) {
                    b[s][kc][0] = *(const unsigned*)(bp + kc * 32);
                    b[s][kc][1] = *(const unsigned*)(bp + kc * 32 + 16);
                }
            }

            unsigned racc0[4] = {0, 0, 0, 0};
            unsigned racc1[4] = {0, 0, 0, 0};
            unsigned cacc[4]  = {0, 0, 0, 0};

            unsigned d[2][2];
            d[0][0] = 0; d[0][1] = 0;
            MMA_PAIR(d[0][0], d[0][1], a[0], b[0]);
#pragma unroll
            for (int i = 1; i < 16; i++) {
                int s = i >> 2, mf = i & 3;
                int pi = i - 1, ps = pi >> 2, pmf = pi & 3;
                d[i & 1][0] = 0; d[i & 1][1] = 0;
                MMA_PAIR(d[i & 1][0], d[i & 1][1], a[mf], b[s]);
                CONSUME(d[pi & 1][0], d[pi & 1][1], pmf, ps);
            }
            CONSUME(d[1][0], d[1][1], 3, 3);

#pragma unroll
            for (int mf = 0; mf < 4; mf++) {
                float2 f0 = __half22float2(*reinterpret_cast<__half2*>(&racc0[mf]));
                float2 f1 = __half22float2(*reinterpret_cast<__half2*>(&racc1[mf]));
                float v0 = f0.x + f0.y;
                float v1 = f1.x + f1.y;
                v0 += __shfl_xor_sync(0xffffffffu, v0, 1);
                v0 += __shfl_xor_sync(0xffffffffu, v0, 2);
                v1 += __shfl_xor_sync(0xffffffffu, v1, 1);
                v1 += __shfl_xor_sync(0xffffffffu, v1, 2);
                if (tig == 0) {
                    red[buf][rbase + mf * 16 + g][c]     = v0;
                    red[buf][rbase + mf * 16 + 8 + g][c] = v1;
                }
            }
#pragma unroll
            for (int s = 0; s < 4; s++) {
                float2 cf = __half22float2(*reinterpret_cast<__half2*>(&cacc[s]));
#pragma unroll
                for (int h = 0; h < 2; h++) {
                    float v = h ? cf.y : cf.x;
                    v += __shfl_xor_sync(0xffffffffu, v, 4);
                    v += __shfl_xor_sync(0xffffffffu, v, 8);
                    v += __shfl_xor_sync(0xffffffffu, v, 16);
                    if (g == 0)
                        cred[buf][(c + s * 4) * 8 + tig * 2 + h][r] = v;
                }
            }
            __syncthreads();

            if (tid < 128) {
                const float* rp = red[buf][tid];
                atomicAdd(&g_RS[I * 128 + tid], rp[0] + rp[1] + rp[2] + rp[3]);
                if (I != J) {
                    const float* cp = cred[buf][tid];
                    atomicAdd(&g_RS[J * 128 + tid], cp[0] + cp[1]);
                }
            }
            I = nI; J = nJ;
        }
    }
    grid_barrier();                            // g_RS complete

    // ---------------- Phase 3: pair ratios + loss ------------------------
    {
        int gid = blockIdx.x * 256 + tid;      // pair index (first 8192 work)
        float ratio = 0.f;
        if (gid < NR / 2) {
            const uint4* yp = (const uint4*)g_Y + (size_t)gid * 16;
            float dot = 0.f;
#pragma unroll
            for (int k = 0; k < 8; k++) {
                uint4 ua = yp[k];
                uint4 ub = yp[8 + k];
                const __half2* ha = (const __half2*)&ua;
                const __half2* hb = (const __half2*)&ub;
#pragma unroll
                for (int q = 0; q < 4; q++) {
                    float2 fa = __half22float2(ha[q]);
                    float2 fb = __half22float2(hb[q]);
                    dot += fa.x * fb.x + fa.y * fb.y;
                }
            }
            float num = exp2f(dot);
            float2 den = ((const float2*)g_RS)[gid];
            ratio = num / (den.x - E2C) + num / (den.y - E2C);
        }
#pragma unroll
        for (int o = 16; o > 0; o >>= 1) ratio += __shfl_xor_sync(0xffffffffu, ratio, o);
        if (lane == 0) red[0][warp][0] = ratio;
        __syncthreads();
        if (tid == 0) {
            float v = red[0][0][0] + red[0][1][0] + red[0][2][0] + red[0][3][0] +
                      red[0][4][0] + red[0][5][0] + red[0][6][0] + red[0][7][0];
            atomicAdd(&g_sum, v);
            __threadfence();
            if (atomicAdd(&g_cnt, 1u) == NCTA - 1) {   // last block finalizes
                float total = *((volatile float*)&g_sum);
                out[0] = -logf(total * (1.0f / (float)NR));
                g_sum = 0.f;
                g_cnt = 0u;
            }
        }
    }
}

// ---------------------------------------------------------------------------
extern "C" void kernel_launch(void* const* d_in, const int* in_sizes, int n_in,
                              void* d_out, int out_size) {
    const float* x = (const float*)d_in[0];
    k_all<<<NCTA, 256>>>(x, (float*)d_out);
}